// round 12
// baseline (speedup 1.0000x reference)
#include <cuda_runtime.h>
#include <cuda_fp16.h>
#include <math.h>

#define N_NODES 100000
#define N_EDGES 3200000
#define FULLM 0xffffffffu
#define TB 256
#define EB ((N_EDGES + TB - 1) / TB)                  // edge blocks (12500)
#define G1B ((N_NODES + 7) / 8)                       // gemm1 warp blocks (12500)
#define CAP 64                                        // bin slots per node
#define OVF_CAP 32768

// ---------------- device scratch ----------------------------------------------
__device__ int    g_is64;
__device__ int    g_cnt[N_NODES];
__device__ int    g_bins[N_NODES * CAP];  // src ids, bins[d*64 + r]
__device__ int    g_ovf_cnt;
__device__ int    g_ovf_d[OVF_CAP];
__device__ int    g_ovf_s[OVF_CAP];
__device__ float  g_dinv[N_NODES];
__device__ __half g_H1[N_NODES * 64];   // layer-1 gather buf (128B rows)
__device__ __half g_H2[N_NODES * 32];   // layer-2 gather buf (64B rows)
__device__ __half g_H3[N_NODES * 16];   // layer-3 gather buf (32B rows)
__device__ float  g_H4[N_NODES * 8];    // layer-4 gather buf (32B rows, fp32)

__device__ __forceinline__ void acc_int2(int2 v, float& a0, float& a1,
                                         float& a2, float& a3) {
    float2 f0 = __half22float2(*(__half2*)&v.x);
    float2 f1 = __half22float2(*(__half2*)&v.y);
    a0 += f0.x; a1 += f0.y; a2 += f1.x; a3 += f1.y;
}

// ---------------- init: zero cnt + ovf + dtype detect ---------------------------
__global__ __launch_bounds__(TB) void k_init(const void* ei) {
    int i = blockIdx.x * blockDim.x + threadIdx.x;
    if (i < N_NODES) g_cnt[i] = 0;
    if (blockIdx.x == 0) {
        __shared__ int any_nz;
        if (threadIdx.x == 0) { any_nz = 0; g_ovf_cnt = 0; }
        __syncthreads();
        const int* w = (const int*)ei;
        for (int k = threadIdx.x; k < 4096; k += blockDim.x)
            if (w[2 * k + 1] != 0) any_nz = 1;
        __syncthreads();
        if (threadIdx.x == 0) g_is64 = any_nz ? 0 : 1;
    }
}

// ---------------- count + direct bin fill ----------------------------------------
__global__ void k_count_fill(const void* __restrict__ ei) {
    int e = blockIdx.x * blockDim.x + threadIdx.x;
    if (e < N_EDGES) {
        int is64 = g_is64;
        int s, d;
        if (is64) {
            s = (int)((const long long*)ei)[e];
            d = (int)((const long long*)ei)[(long long)N_EDGES + e];
        } else {
            s = ((const int*)ei)[e];
            d = ((const int*)ei)[N_EDGES + e];
        }
        if ((unsigned)d < N_NODES) {
            int r = atomicAdd(&g_cnt[d], 1);
            if (r < CAP) {
                g_bins[d * CAP + r] = s;
            } else {
                int o = atomicAdd(&g_ovf_cnt, 1);
                if (o < OVF_CAP) { g_ovf_d[o] = d; g_ovf_s[o] = s; }
            }
        }
    }
}

// ---------------- gemm1 (warp per node) + dinv ------------------------------------
__global__ __launch_bounds__(TB) void k_gemm1(
    const float* __restrict__ x, const float* __restrict__ W)
{
    __shared__ float2 sW2[34 * 32];   // sW2[k*32+j] = W[k][2j..2j+1]
    for (int i = threadIdx.x; i < 34 * 32; i += blockDim.x) {
        int k = i >> 5, j = i & 31;
        sW2[i] = make_float2(W[k * 64 + 2 * j], W[k * 64 + 2 * j + 1]);
    }
    __syncthreads();
    int warp = blockIdx.x * 8 + (threadIdx.x >> 5);
    int lane = threadIdx.x & 31;
    if (warp >= N_NODES) return;
    const int node = warp;

    const float2* xr = (const float2*)(x + (size_t)node * 34);
    float2 xv = (lane < 17) ? xr[lane] : make_float2(0.f, 0.f);

    float a0 = 0.f, a1 = 0.f;
#pragma unroll
    for (int k = 0; k < 17; k++) {
        float x0 = __shfl_sync(FULLM, xv.x, k);
        float x1 = __shfl_sync(FULLM, xv.y, k);
        float2 w0 = sW2[(2 * k) * 32 + lane];
        float2 w1 = sW2[(2 * k + 1) * 32 + lane];
        a0 += x0 * w0.x + x1 * w1.x;
        a1 += x0 * w0.y + x1 * w1.y;
    }
    float dv = rsqrtf((float)g_cnt[node] + 1.0f);   // +1 self loop
    if (lane == 0) g_dinv[node] = dv;
    ((__half2*)g_H1)[(size_t)node * 32 + lane] =
        __floats2half2_rn(a0 * dv, a1 * dv);
}

// ---------------- F1: aggregate 64d (int2 loads, 2 edges/ldg) + GEMM 64->32 ------
__global__ __launch_bounds__(256) void k_f1(
    const float* __restrict__ b1, const float* __restrict__ W2)
{
    __shared__ float2 sW[32 * 32];   // sW[k*32+f] = (W2[2k][f], W2[2k+1][f]) 8KB
    for (int i = threadIdx.x; i < 32 * 32; i += blockDim.x) {
        int k = i >> 5, f = i & 31;
        sW[i] = make_float2(W2[(2 * k) * 32 + f], W2[(2 * k + 1) * 32 + f]);
    }
    __syncthreads();

    int warp = (blockIdx.x * blockDim.x + threadIdx.x) >> 5;
    int lane = threadIdx.x & 31;
    if (warp >= N_NODES) return;
    const int node = warp;
    const int2* rows = (const int2*)g_H1;   // 16 int2 per row
    int sub = lane >> 4;                     // 0/1
    int c   = lane & 15;

    float a0 = 0.f, a1 = 0.f, a2 = 0.f, a3 = 0.f;
    if (sub == 0)
        acc_int2(rows[(size_t)node * 16 + c], a0, a1, a2, a3);  // self loop

    int deg = g_cnt[node];
    int m = min(deg, CAP);
    const int* bin = g_bins + node * CAP;
    int e0 = 0;
    for (; e0 + 32 <= m; e0 += 32) {
        int s = bin[e0 + lane];
#pragma unroll
        for (int j = 0; j < 32; j += 2) {
            int sj = __shfl_sync(FULLM, s, j + sub);
            acc_int2(rows[(size_t)sj * 16 + c], a0, a1, a2, a3);
        }
    }
    if (e0 < m) {
        int mm = m - e0;
        int s = (e0 + lane < m) ? bin[e0 + lane] : 0;
        for (int j = 0; j < mm; j += 2) {
            int idx = j + sub;
            int sj = __shfl_sync(FULLM, s, idx & 31);
            if (idx < mm)
                acc_int2(rows[(size_t)sj * 16 + c], a0, a1, a2, a3);
        }
    }
    int L = g_ovf_cnt; if (L > OVF_CAP) L = OVF_CAP;
    for (int i = 0; i < L; i++) {
        if (g_ovf_d[i] == node && sub == 0)
            acc_int2(rows[(size_t)g_ovf_s[i] * 16 + c], a0, a1, a2, a3);
    }

    // combine the two edge-subgroups
    a0 += __shfl_xor_sync(FULLM, a0, 16);
    a1 += __shfl_xor_sync(FULLM, a1, 16);
    a2 += __shfl_xor_sync(FULLM, a2, 16);
    a3 += __shfl_xor_sync(FULLM, a3, 16);
    // redistribute: lane l takes features [2l, 2l+1] from lane l>>1
    int srcl = lane >> 1;
    float f0 = __shfl_sync(FULLM, a0, srcl);
    float f1 = __shfl_sync(FULLM, a1, srcl);
    float f2 = __shfl_sync(FULLM, a2, srcl);
    float f3 = __shfl_sync(FULLM, a3, srcl);
    float sx = (lane & 1) ? f2 : f0;
    float sy = (lane & 1) ? f3 : f1;

    float d = g_dinv[node];
    float2 bv = ((const float2*)b1)[lane];
    float hx = tanhf(d * sx + bv.x);   // h1[2*lane]
    float hy = tanhf(d * sy + bv.y);   // h1[2*lane+1]

    // GEMM 64->32 (packed float2 weights)
    float acc = 0.f;
#pragma unroll
    for (int k = 0; k < 32; k++) {
        float x0 = __shfl_sync(FULLM, hx, k);
        float x1 = __shfl_sync(FULLM, hy, k);
        float2 w = sW[k * 32 + lane];
        acc += x0 * w.x + x1 * w.y;
    }
    g_H2[(size_t)node * 32 + lane] = __float2half(acc * d);
}

// ---------------- F2: aggregate 32d (int2 loads, 4 edges/ldg) + GEMM 32->16 ------
__global__ __launch_bounds__(256) void k_f2(
    const float* __restrict__ b2, const float* __restrict__ W3)
{
    __shared__ float2 sW[16 * 16];   // sW[k*16+f] = (W3[2k][f], W3[2k+1][f]) 2KB
    for (int i = threadIdx.x; i < 16 * 16; i += blockDim.x) {
        int k = i >> 4, f = i & 15;
        sW[i] = make_float2(W3[(2 * k) * 16 + f], W3[(2 * k + 1) * 16 + f]);
    }
    __syncthreads();

    int warp = (blockIdx.x * blockDim.x + threadIdx.x) >> 5;
    int lane = threadIdx.x & 31;
    if (warp >= N_NODES) return;
    const int node = warp;
    const int2* rows = (const int2*)g_H2;   // 8 int2 per row
    int sub = lane >> 3;                     // 0..3
    int c   = lane & 7;

    float a0 = 0.f, a1 = 0.f, a2 = 0.f, a3 = 0.f;
    if (sub == 0)
        acc_int2(rows[(size_t)node * 8 + c], a0, a1, a2, a3);   // self loop

    int deg = g_cnt[node];
    int m = min(deg, CAP);
    const int* bin = g_bins + node * CAP;
    int e0 = 0;
    for (; e0 + 32 <= m; e0 += 32) {
        int s = bin[e0 + lane];
#pragma unroll
        for (int j = 0; j < 32; j += 4) {
            int sj = __shfl_sync(FULLM, s, j + sub);
            acc_int2(rows[(size_t)sj * 8 + c], a0, a1, a2, a3);
        }
    }
    if (e0 < m) {
        int mm = m - e0;
        int s = (e0 + lane < m) ? bin[e0 + lane] : 0;
        for (int j = 0; j < mm; j += 4) {
            int idx = j + sub;
            int sj = __shfl_sync(FULLM, s, idx & 31);
            if (idx < mm)
                acc_int2(rows[(size_t)sj * 8 + c], a0, a1, a2, a3);
        }
    }
    int L = g_ovf_cnt; if (L > OVF_CAP) L = OVF_CAP;
    for (int i = 0; i < L; i++) {
        if (g_ovf_d[i] == node && sub == 0)
            acc_int2(rows[(size_t)g_ovf_s[i] * 8 + c], a0, a1, a2, a3);
    }

    // combine 4 subgroups
#pragma unroll
    for (int off = 8; off < 32; off <<= 1) {
        a0 += __shfl_xor_sync(FULLM, a0, off);
        a1 += __shfl_xor_sync(FULLM, a1, off);
        a2 += __shfl_xor_sync(FULLM, a2, off);
        a3 += __shfl_xor_sync(FULLM, a3, off);
    }
    // redistribute: lane l (0..15) takes features [2l, 2l+1] from lane l>>1
    int srcl = (lane & 15) >> 1;
    float f0 = __shfl_sync(FULLM, a0, srcl);
    float f1 = __shfl_sync(FULLM, a1, srcl);
    float f2 = __shfl_sync(FULLM, a2, srcl);
    float f3 = __shfl_sync(FULLM, a3, srcl);
    float sx = (lane & 1) ? f2 : f0;
    float sy = (lane & 1) ? f3 : f1;

    float d = g_dinv[node];
    float2 bv = ((const float2*)b2)[lane & 15];
    float hx = tanhf(d * sx + bv.x);   // h2[2*(lane&15)]
    float hy = tanhf(d * sy + bv.y);

    // GEMM 32->16: lanes 0..15 compute f = lane
    float acc = 0.f;
#pragma unroll
    for (int k = 0; k < 16; k++) {
        float x0 = __shfl_sync(FULLM, hx, k);
        float x1 = __shfl_sync(FULLM, hy, k);
        float2 w = sW[k * 16 + (lane & 15)];
        acc += x0 * w.x + x1 * w.y;
    }
    if (lane < 16)
        g_H3[(size_t)node * 16 + lane] = __float2half(acc * d);
}

// ---------------- F3: aggregate 16d (int2 loads, 8 edges/ldg) + GEMM 16->8 -------
__global__ __launch_bounds__(256) void k_f3(
    const float* __restrict__ b3, const float* __restrict__ W4)
{
    __shared__ float2 sW[8 * 8];   // sW[k*8+f] = (W4[2k][f], W4[2k+1][f])
    for (int i = threadIdx.x; i < 8 * 8; i += blockDim.x) {
        int k = i >> 3, f = i & 7;
        sW[i] = make_float2(W4[(2 * k) * 8 + f], W4[(2 * k + 1) * 8 + f]);
    }
    __syncthreads();

    int warp = (blockIdx.x * blockDim.x + threadIdx.x) >> 5;
    int lane = threadIdx.x & 31;
    if (warp >= N_NODES) return;
    const int node = warp;
    const int2* rows = (const int2*)g_H3;   // 4 int2 per row
    int sub = lane >> 2;                     // 0..7
    int c   = lane & 3;

    float a0 = 0.f, a1 = 0.f, a2 = 0.f, a3 = 0.f;
    if (sub == 0)
        acc_int2(rows[(size_t)node * 4 + c], a0, a1, a2, a3);   // self loop

    int deg = g_cnt[node];
    int m = min(deg, CAP);
    const int* bin = g_bins + node * CAP;
    int e0 = 0;
    for (; e0 + 32 <= m; e0 += 32) {
        int s = bin[e0 + lane];
#pragma unroll
        for (int j = 0; j < 32; j += 8) {
            int sj = __shfl_sync(FULLM, s, j + sub);
            acc_int2(rows[(size_t)sj * 4 + c], a0, a1, a2, a3);
        }
    }
    if (e0 < m) {
        int mm = m - e0;
        int s = (e0 + lane < m) ? bin[e0 + lane] : 0;
        for (int j = 0; j < mm; j += 8) {
            int idx = j + sub;
            int sj = __shfl_sync(FULLM, s, idx & 31);
            if (idx < mm)
                acc_int2(rows[(size_t)sj * 4 + c], a0, a1, a2, a3);
        }
    }
    int L = g_ovf_cnt; if (L > OVF_CAP) L = OVF_CAP;
    for (int i = 0; i < L; i++) {
        if (g_ovf_d[i] == node && sub == 0)
            acc_int2(rows[(size_t)g_ovf_s[i] * 4 + c], a0, a1, a2, a3);
    }

    // combine 8 subgroups
#pragma unroll
    for (int off = 4; off < 32; off <<= 1) {
        a0 += __shfl_xor_sync(FULLM, a0, off);
        a1 += __shfl_xor_sync(FULLM, a1, off);
        a2 += __shfl_xor_sync(FULLM, a2, off);
        a3 += __shfl_xor_sync(FULLM, a3, off);
    }
    // redistribute: lane l (0..7) takes features [2l, 2l+1] from lane l>>1
    int srcl = (lane & 7) >> 1;
    float f0 = __shfl_sync(FULLM, a0, srcl);
    float f1 = __shfl_sync(FULLM, a1, srcl);
    float f2 = __shfl_sync(FULLM, a2, srcl);
    float f3 = __shfl_sync(FULLM, a3, srcl);
    float sx = (lane & 1) ? f2 : f0;
    float sy = (lane & 1) ? f3 : f1;

    float d = g_dinv[node];
    float2 bv = ((const float2*)b3)[lane & 7];
    float hx = tanhf(d * sx + bv.x);   // h3[2*(lane&7)]
    float hy = tanhf(d * sy + bv.y);

    // GEMM 16->8: lanes 0..7 compute f = lane
    float acc = 0.f;
#pragma unroll
    for (int k = 0; k < 8; k++) {
        float x0 = __shfl_sync(FULLM, hx, k);
        float x1 = __shfl_sync(FULLM, hy, k);
        float2 w = sW[k * 8 + (lane & 7)];
        acc += x0 * w.x + x1 * w.y;
    }
    if (lane < 8)
        g_H4[(size_t)node * 8 + lane] = acc * d;
}

// ---------------- F4: aggregate 8d (fp32) + tanh + classifier -> d_out ----------
// d_out: [N*2 logits][N*8 hidden]
__global__ __launch_bounds__(256) void k_f4(
    const float* __restrict__ b4, const float* __restrict__ Wc,
    const float* __restrict__ bc, float* __restrict__ dout)
{
    int warp = (blockIdx.x * blockDim.x + threadIdx.x) >> 5;
    int lane = threadIdx.x & 31;
    if (warp >= N_NODES) return;
    const int node = warp;
    const float2* t = (const float2*)g_H4;
    int sub = lane >> 2;          // 8 subgroups
    int c   = lane & 3;

    float ax = 0.f, ay = 0.f, bx = 0.f, by = 0.f;
    if (sub == 0) {
        float2 s = t[(size_t)node * 4 + c];
        ax = s.x; ay = s.y;
    }
    int deg = g_cnt[node];
    int m = min(deg, CAP);
    const int* bin = g_bins + node * CAP;
    int e = sub;
    for (; e + 24 < m; e += 32) {
        int s0 = bin[e];
        int s1 = bin[e + 8];
        int s2 = bin[e + 16];
        int s3 = bin[e + 24];
        float2 r0 = t[(size_t)s0 * 4 + c];
        float2 r1 = t[(size_t)s1 * 4 + c];
        float2 r2 = t[(size_t)s2 * 4 + c];
        float2 r3 = t[(size_t)s3 * 4 + c];
        ax += r0.x; ay += r0.y;
        bx += r1.x; by += r1.y;
        ax += r2.x; ay += r2.y;
        bx += r3.x; by += r3.y;
    }
    for (; e < m; e += 8) {
        float2 r = t[(size_t)bin[e] * 4 + c];
        ax += r.x; ay += r.y;
    }
    int L = g_ovf_cnt; if (L > OVF_CAP) L = OVF_CAP;
    for (int i = 0; i < L; i++) {
        if (g_ovf_d[i] == node && (i & 7) == sub) {
            float2 r = t[(size_t)g_ovf_s[i] * 4 + c];
            ax += r.x; ay += r.y;
        }
    }
    ax += bx; ay += by;
    ax += __shfl_xor_sync(FULLM, ax, 4);
    ay += __shfl_xor_sync(FULLM, ay, 4);
    ax += __shfl_xor_sync(FULLM, ax, 8);
    ay += __shfl_xor_sync(FULLM, ay, 8);
    ax += __shfl_xor_sync(FULLM, ax, 16);
    ay += __shfl_xor_sync(FULLM, ay, 16);

    float d = g_dinv[node];
    float hx = tanhf(d * ax + b4[2 * c]);      // h4[2c]
    float hy = tanhf(d * ay + b4[2 * c + 1]);  // h4[2c+1]

    float p0 = hx * Wc[(2 * c) * 2 + 0] + hy * Wc[(2 * c + 1) * 2 + 0];
    float p1 = hx * Wc[(2 * c) * 2 + 1] + hy * Wc[(2 * c + 1) * 2 + 1];
    p0 += __shfl_xor_sync(FULLM, p0, 1);
    p1 += __shfl_xor_sync(FULLM, p1, 1);
    p0 += __shfl_xor_sync(FULLM, p0, 2);
    p1 += __shfl_xor_sync(FULLM, p1, 2);

    if (sub == 0) {
        float2* dh = (float2*)(dout + (size_t)2 * N_NODES);
        dh[(size_t)node * 4 + c] = make_float2(hx, hy);
        if (c == 0) {
            dout[(size_t)node * 2 + 0] = p0 + bc[0];
            dout[(size_t)node * 2 + 1] = p1 + bc[1];
        }
    }
}

// ---------------- launcher --------------------------------------------------------
extern "C" void kernel_launch(void* const* d_in, const int* in_sizes, int n_in,
                              void* d_out, int out_size)
{
    const float* x  = (const float*)d_in[0];
    const void*  ei = d_in[1];
    const float* W1 = (const float*)d_in[2];
    const float* b1 = (const float*)d_in[3];
    const float* W2 = (const float*)d_in[4];
    const float* b2 = (const float*)d_in[5];
    const float* W3 = (const float*)d_in[6];
    const float* b3 = (const float*)d_in[7];
    const float* W4 = (const float*)d_in[8];
    const float* b4 = (const float*)d_in[9];
    const float* Wc = (const float*)d_in[10];
    const float* bc = (const float*)d_in[11];
    float* out = (float*)d_out;

    const int nb = (N_NODES + TB - 1) / TB;
    const int wb = (N_NODES * 32 + TB - 1) / TB;  // one warp per node

    k_init<<<nb, TB>>>(ei);            // 0
    k_count_fill<<<EB, TB>>>(ei);      // 1
    k_gemm1<<<G1B, TB>>>(x, W1);       // 2
    k_f1<<<wb, TB>>>(b1, W2);          // 3  (profiled)
    k_f2<<<wb, TB>>>(b2, W3);          // 4
    k_f3<<<wb, TB>>>(b3, W4);          // 5
    k_f4<<<wb, TB>>>(b4, Wc, bc, out); // 6
}

// round 13
// speedup vs baseline: 1.0288x; 1.0288x over previous
#include <cuda_runtime.h>
#include <cuda_fp16.h>
#include <math.h>

#define N_NODES 100000
#define N_EDGES 3200000
#define FULLM 0xffffffffu
#define TB 256
#define EB ((N_EDGES + TB - 1) / TB)                  // edge blocks (12500)
#define G1B ((N_NODES + 7) / 8)                       // gemm1 warp blocks (12500)
#define CAP 64                                        // bin slots per node
#define OVF_CAP 32768

// ---------------- device scratch ----------------------------------------------
__device__ int    g_is64;
__device__ int    g_cnt[N_NODES];
__device__ int    g_bins[N_NODES * CAP];  // src ids, bins[d*64 + r]
__device__ int    g_ovf_cnt;
__device__ int    g_ovf_d[OVF_CAP];
__device__ int    g_ovf_s[OVF_CAP];
__device__ float  g_dinv[N_NODES];
__device__ __half g_H1[N_NODES * 64];   // layer-1 gather buf (128B rows)
__device__ __half g_H2[N_NODES * 32];   // layer-2 gather buf (64B rows)
__device__ __half g_H3[N_NODES * 16];   // layer-3 gather buf (32B rows)
__device__ float  g_H4[N_NODES * 8];    // layer-4 gather buf (32B rows, fp32)

// ---------------- init: zero cnt + ovf + dtype detect ---------------------------
__global__ __launch_bounds__(TB) void k_init(const void* ei) {
    int i = blockIdx.x * blockDim.x + threadIdx.x;
    if (i < N_NODES) g_cnt[i] = 0;
    if (blockIdx.x == 0) {
        __shared__ int any_nz;
        if (threadIdx.x == 0) { any_nz = 0; g_ovf_cnt = 0; }
        __syncthreads();
        const int* w = (const int*)ei;
        for (int k = threadIdx.x; k < 4096; k += blockDim.x)
            if (w[2 * k + 1] != 0) any_nz = 1;
        __syncthreads();
        if (threadIdx.x == 0) g_is64 = any_nz ? 0 : 1;
    }
}

// ---------------- count + direct bin fill ----------------------------------------
__global__ void k_count_fill(const void* __restrict__ ei) {
    int e = blockIdx.x * blockDim.x + threadIdx.x;
    if (e < N_EDGES) {
        int is64 = g_is64;
        int s, d;
        if (is64) {
            s = (int)((const long long*)ei)[e];
            d = (int)((const long long*)ei)[(long long)N_EDGES + e];
        } else {
            s = ((const int*)ei)[e];
            d = ((const int*)ei)[N_EDGES + e];
        }
        if ((unsigned)d < N_NODES) {
            int r = atomicAdd(&g_cnt[d], 1);
            if (r < CAP) {
                g_bins[d * CAP + r] = s;
            } else {
                int o = atomicAdd(&g_ovf_cnt, 1);
                if (o < OVF_CAP) { g_ovf_d[o] = d; g_ovf_s[o] = s; }
            }
        }
    }
}

// ---------------- gemm1 (warp per node) + dinv ------------------------------------
__global__ __launch_bounds__(TB) void k_gemm1(
    const float* __restrict__ x, const float* __restrict__ W)
{
    __shared__ float2 sW2[34 * 32];   // sW2[k*32+j] = W[k][2j..2j+1]
    for (int i = threadIdx.x; i < 34 * 32; i += blockDim.x) {
        int k = i >> 5, j = i & 31;
        sW2[i] = make_float2(W[k * 64 + 2 * j], W[k * 64 + 2 * j + 1]);
    }
    __syncthreads();
    int warp = blockIdx.x * 8 + (threadIdx.x >> 5);
    int lane = threadIdx.x & 31;
    if (warp >= N_NODES) return;
    const int node = warp;

    const float2* xr = (const float2*)(x + (size_t)node * 34);
    float2 xv = (lane < 17) ? xr[lane] : make_float2(0.f, 0.f);

    float a0 = 0.f, a1 = 0.f;
#pragma unroll
    for (int k = 0; k < 17; k++) {
        float x0 = __shfl_sync(FULLM, xv.x, k);
        float x1 = __shfl_sync(FULLM, xv.y, k);
        float2 w0 = sW2[(2 * k) * 32 + lane];
        float2 w1 = sW2[(2 * k + 1) * 32 + lane];
        a0 += x0 * w0.x + x1 * w1.x;
        a1 += x0 * w0.y + x1 * w1.y;
    }
    float dv = rsqrtf((float)g_cnt[node] + 1.0f);   // +1 self loop
    if (lane == 0) g_dinv[node] = dv;
    ((__half2*)g_H1)[(size_t)node * 32 + lane] =
        __floats2half2_rn(a0 * dv, a1 * dv);
}

// ---------------- F1: aggregate 64d (HADD2 pairwise) + GEMM 64->32 -> H2 ---------
__global__ __launch_bounds__(256) void k_f1(
    const float* __restrict__ b1, const float* __restrict__ W2)
{
    __shared__ float2 sW[32 * 32];   // sW[k*32+f] = (W2[2k][f], W2[2k+1][f]) 8KB
    for (int i = threadIdx.x; i < 32 * 32; i += blockDim.x) {
        int k = i >> 5, f = i & 31;
        sW[i] = make_float2(W2[(2 * k) * 32 + f], W2[(2 * k + 1) * 32 + f]);
    }
    __syncthreads();

    int warp = (blockIdx.x * blockDim.x + threadIdx.x) >> 5;
    int lane = threadIdx.x & 31;
    if (warp >= N_NODES) return;
    const int node = warp;
    const __half2* t = (const __half2*)g_H1;

    float2 self = __half22float2(t[(size_t)node * 32 + lane]);
    float ax0 = self.x, ay0 = self.y, ax1 = 0.f, ay1 = 0.f;

    int deg = g_cnt[node];
    int m = min(deg, CAP);
    const int* bin = g_bins + node * CAP;
    int e0 = 0;
    for (; e0 + 32 <= m; e0 += 32) {
        int s = bin[e0 + lane];
#pragma unroll
        for (int j = 0; j < 32; j += 4) {
            int s0 = __shfl_sync(FULLM, s, j);
            int s1 = __shfl_sync(FULLM, s, j + 1);
            int s2 = __shfl_sync(FULLM, s, j + 2);
            int s3 = __shfl_sync(FULLM, s, j + 3);
            __half2 v0 = t[(size_t)s0 * 32 + lane];
            __half2 v1 = t[(size_t)s1 * 32 + lane];
            __half2 v2 = t[(size_t)s2 * 32 + lane];
            __half2 v3 = t[(size_t)s3 * 32 + lane];
            float2 p0 = __half22float2(__hadd2(v0, v1));
            float2 p1 = __half22float2(__hadd2(v2, v3));
            ax0 += p0.x; ay0 += p0.y;
            ax1 += p1.x; ay1 += p1.y;
        }
    }
    if (e0 < m) {
        int mm = m - e0;
        int s = (e0 + lane < m) ? bin[e0 + lane] : 0;
        for (int j = 0; j < mm; j++) {
            int sj = __shfl_sync(FULLM, s, j);
            float2 r = __half22float2(t[(size_t)sj * 32 + lane]);
            ax0 += r.x; ay0 += r.y;
        }
    }
    int L = g_ovf_cnt; if (L > OVF_CAP) L = OVF_CAP;
    for (int i = 0; i < L; i++) {
        if (g_ovf_d[i] == node) {
            float2 r = __half22float2(t[(size_t)g_ovf_s[i] * 32 + lane]);
            ax0 += r.x; ay0 += r.y;
        }
    }

    float d = g_dinv[node];
    float2 bv = ((const float2*)b1)[lane];
    float hx = tanhf(d * (ax0 + ax1) + bv.x);   // h1[2*lane]
    float hy = tanhf(d * (ay0 + ay1) + bv.y);   // h1[2*lane+1]

    // GEMM 64->32 (packed float2 weights)
    float acc = 0.f;
#pragma unroll
    for (int k = 0; k < 32; k++) {
        float x0 = __shfl_sync(FULLM, hx, k);
        float x1 = __shfl_sync(FULLM, hy, k);
        float2 w = sW[k * 32 + lane];
        acc += x0 * w.x + x1 * w.y;
    }
    g_H2[(size_t)node * 32 + lane] = __float2half(acc * d);
}

// ---------------- F2: aggregate 32d (HADD2 pairwise) + GEMM 32->16 -> H3 ---------
__global__ __launch_bounds__(256) void k_f2(
    const float* __restrict__ b2, const float* __restrict__ W3)
{
    __shared__ float sW[32 * 16];
    for (int i = threadIdx.x; i < 32 * 16; i += blockDim.x) sW[i] = W3[i];
    __syncthreads();

    int warp = (blockIdx.x * blockDim.x + threadIdx.x) >> 5;
    int lane = threadIdx.x & 31;
    if (warp >= N_NODES) return;
    const int node = warp;
    const __half2* t = (const __half2*)g_H2;
    int sub = lane >> 4;          // 2 subgroups
    int c   = lane & 15;

    float ax = 0.f, ay = 0.f, bx = 0.f, by = 0.f;
    if (sub == 0) {
        float2 s = __half22float2(t[(size_t)node * 16 + c]);
        ax = s.x; ay = s.y;
    }
    int deg = g_cnt[node];
    int m = min(deg, CAP);
    const int* bin = g_bins + node * CAP;
    int e = sub;
    for (; e + 14 < m; e += 16) {
        int s0 = bin[e];
        int s1 = bin[e + 2];
        int s2 = bin[e + 4];
        int s3 = bin[e + 6];
        int s4 = bin[e + 8];
        int s5 = bin[e + 10];
        int s6 = bin[e + 12];
        int s7 = bin[e + 14];
        __half2 v0 = t[(size_t)s0 * 16 + c];
        __half2 v1 = t[(size_t)s1 * 16 + c];
        __half2 v2 = t[(size_t)s2 * 16 + c];
        __half2 v3 = t[(size_t)s3 * 16 + c];
        __half2 v4 = t[(size_t)s4 * 16 + c];
        __half2 v5 = t[(size_t)s5 * 16 + c];
        __half2 v6 = t[(size_t)s6 * 16 + c];
        __half2 v7 = t[(size_t)s7 * 16 + c];
        float2 p0 = __half22float2(__hadd2(v0, v1));
        float2 p1 = __half22float2(__hadd2(v2, v3));
        float2 p2 = __half22float2(__hadd2(v4, v5));
        float2 p3 = __half22float2(__hadd2(v6, v7));
        ax += p0.x; ay += p0.y;  bx += p1.x; by += p1.y;
        ax += p2.x; ay += p2.y;  bx += p3.x; by += p3.y;
    }
    for (; e < m; e += 2) {
        float2 r = __half22float2(t[(size_t)bin[e] * 16 + c]);
        ax += r.x; ay += r.y;
    }
    int L = g_ovf_cnt; if (L > OVF_CAP) L = OVF_CAP;
    for (int i = 0; i < L; i++) {
        if (g_ovf_d[i] == node && (i & 1) == sub) {
            float2 r = __half22float2(t[(size_t)g_ovf_s[i] * 16 + c]);
            ax += r.x; ay += r.y;
        }
    }
    ax += bx; ay += by;
    ax += __shfl_xor_sync(FULLM, ax, 16);
    ay += __shfl_xor_sync(FULLM, ay, 16);

    float d = g_dinv[node];
    float2 bv = ((const float2*)b2)[c];
    float hx = tanhf(d * ax + bv.x);    // h2[2c]
    float hy = tanhf(d * ay + bv.y);    // h2[2c+1]

    // GEMM 32->16: lanes 0..15 compute f = c
    float acc = 0.f;
#pragma unroll
    for (int k = 0; k < 16; k++) {
        float x0 = __shfl_sync(FULLM, hx, k);
        float x1 = __shfl_sync(FULLM, hy, k);
        acc += x0 * sW[(2 * k) * 16 + c] + x1 * sW[(2 * k + 1) * 16 + c];
    }
    if (sub == 0)
        g_H3[(size_t)node * 16 + c] = __float2half(acc * d);
}

// ---------------- F3: aggregate 16d (HADD2 pairwise) + GEMM 16->8 -> H4 ----------
__global__ __launch_bounds__(256) void k_f3(
    const float* __restrict__ b3, const float* __restrict__ W4)
{
    __shared__ float sW[16 * 8];
    for (int i = threadIdx.x; i < 16 * 8; i += blockDim.x) sW[i] = W4[i];
    __syncthreads();

    int warp = (blockIdx.x * blockDim.x + threadIdx.x) >> 5;
    int lane = threadIdx.x & 31;
    if (warp >= N_NODES) return;
    const int node = warp;
    const __half2* t = (const __half2*)g_H3;
    int sub = lane >> 3;          // 4 subgroups
    int c   = lane & 7;

    float ax = 0.f, ay = 0.f, bx = 0.f, by = 0.f;
    if (sub == 0) {
        float2 s = __half22float2(t[(size_t)node * 8 + c]);
        ax = s.x; ay = s.y;
    }
    int deg = g_cnt[node];
    int m = min(deg, CAP);
    const int* bin = g_bins + node * CAP;
    int e = sub;
    for (; e + 28 < m; e += 32) {
        int s0 = bin[e];
        int s1 = bin[e + 4];
        int s2 = bin[e + 8];
        int s3 = bin[e + 12];
        int s4 = bin[e + 16];
        int s5 = bin[e + 20];
        int s6 = bin[e + 24];
        int s7 = bin[e + 28];
        __half2 v0 = t[(size_t)s0 * 8 + c];
        __half2 v1 = t[(size_t)s1 * 8 + c];
        __half2 v2 = t[(size_t)s2 * 8 + c];
        __half2 v3 = t[(size_t)s3 * 8 + c];
        __half2 v4 = t[(size_t)s4 * 8 + c];
        __half2 v5 = t[(size_t)s5 * 8 + c];
        __half2 v6 = t[(size_t)s6 * 8 + c];
        __half2 v7 = t[(size_t)s7 * 8 + c];
        float2 p0 = __half22float2(__hadd2(v0, v1));
        float2 p1 = __half22float2(__hadd2(v2, v3));
        float2 p2 = __half22float2(__hadd2(v4, v5));
        float2 p3 = __half22float2(__hadd2(v6, v7));
        ax += p0.x; ay += p0.y;  bx += p1.x; by += p1.y;
        ax += p2.x; ay += p2.y;  bx += p3.x; by += p3.y;
    }
    for (; e < m; e += 4) {
        float2 r = __half22float2(t[(size_t)bin[e] * 8 + c]);
        ax += r.x; ay += r.y;
    }
    int L = g_ovf_cnt; if (L > OVF_CAP) L = OVF_CAP;
    for (int i = 0; i < L; i++) {
        if (g_ovf_d[i] == node && (i & 3) == sub) {
            float2 r = __half22float2(t[(size_t)g_ovf_s[i] * 8 + c]);
            ax += r.x; ay += r.y;
        }
    }
    ax += bx; ay += by;
    ax += __shfl_xor_sync(FULLM, ax, 8);
    ay += __shfl_xor_sync(FULLM, ay, 8);
    ax += __shfl_xor_sync(FULLM, ax, 16);
    ay += __shfl_xor_sync(FULLM, ay, 16);

    float d = g_dinv[node];
    float2 bv = ((const float2*)b3)[c];
    float hx = tanhf(d * ax + bv.x);    // h3[2c]
    float hy = tanhf(d * ay + bv.y);

    // GEMM 16->8: lanes 0..7 compute f = c
    float acc = 0.f;
#pragma unroll
    for (int k = 0; k < 8; k++) {
        float x0 = __shfl_sync(FULLM, hx, k);
        float x1 = __shfl_sync(FULLM, hy, k);
        acc += x0 * sW[(2 * k) * 8 + c] + x1 * sW[(2 * k + 1) * 8 + c];
    }
    if (sub == 0)
        g_H4[(size_t)node * 8 + c] = acc * d;
}

// ---------------- F4: aggregate 8d (fp32) + tanh + classifier -> d_out ----------
// d_out: [N*2 logits][N*8 hidden]
__global__ __launch_bounds__(256) void k_f4(
    const float* __restrict__ b4, const float* __restrict__ Wc,
    const float* __restrict__ bc, float* __restrict__ dout)
{
    int warp = (blockIdx.x * blockDim.x + threadIdx.x) >> 5;
    int lane = threadIdx.x & 31;
    if (warp >= N_NODES) return;
    const int node = warp;
    const float2* t = (const float2*)g_H4;
    int sub = lane >> 2;          // 8 subgroups
    int c   = lane & 3;

    float ax = 0.f, ay = 0.f, bx = 0.f, by = 0.f;
    if (sub == 0) {
        float2 s = t[(size_t)node * 4 + c];
        ax = s.x; ay = s.y;
    }
    int deg = g_cnt[node];
    int m = min(deg, CAP);
    const int* bin = g_bins + node * CAP;
    int e = sub;
    for (; e + 24 < m; e += 32) {
        int s0 = bin[e];
        int s1 = bin[e + 8];
        int s2 = bin[e + 16];
        int s3 = bin[e + 24];
        float2 r0 = t[(size_t)s0 * 4 + c];
        float2 r1 = t[(size_t)s1 * 4 + c];
        float2 r2 = t[(size_t)s2 * 4 + c];
        float2 r3 = t[(size_t)s3 * 4 + c];
        ax += r0.x; ay += r0.y;
        bx += r1.x; by += r1.y;
        ax += r2.x; ay += r2.y;
        bx += r3.x; by += r3.y;
    }
    for (; e < m; e += 8) {
        float2 r = t[(size_t)bin[e] * 4 + c];
        ax += r.x; ay += r.y;
    }
    int L = g_ovf_cnt; if (L > OVF_CAP) L = OVF_CAP;
    for (int i = 0; i < L; i++) {
        if (g_ovf_d[i] == node && (i & 7) == sub) {
            float2 r = t[(size_t)g_ovf_s[i] * 4 + c];
            ax += r.x; ay += r.y;
        }
    }
    ax += bx; ay += by;
    ax += __shfl_xor_sync(FULLM, ax, 4);
    ay += __shfl_xor_sync(FULLM, ay, 4);
    ax += __shfl_xor_sync(FULLM, ax, 8);
    ay += __shfl_xor_sync(FULLM, ay, 8);
    ax += __shfl_xor_sync(FULLM, ax, 16);
    ay += __shfl_xor_sync(FULLM, ay, 16);

    float d = g_dinv[node];
    float hx = tanhf(d * ax + b4[2 * c]);      // h4[2c]
    float hy = tanhf(d * ay + b4[2 * c + 1]);  // h4[2c+1]

    float p0 = hx * Wc[(2 * c) * 2 + 0] + hy * Wc[(2 * c + 1) * 2 + 0];
    float p1 = hx * Wc[(2 * c) * 2 + 1] + hy * Wc[(2 * c + 1) * 2 + 1];
    p0 += __shfl_xor_sync(FULLM, p0, 1);
    p1 += __shfl_xor_sync(FULLM, p1, 1);
    p0 += __shfl_xor_sync(FULLM, p0, 2);
    p1 += __shfl_xor_sync(FULLM, p1, 2);

    if (sub == 0) {
        float2* dh = (float2*)(dout + (size_t)2 * N_NODES);
        dh[(size_t)node * 4 + c] = make_float2(hx, hy);
        if (c == 0) {
            dout[(size_t)node * 2 + 0] = p0 + bc[0];
            dout[(size_t)node * 2 + 1] = p1 + bc[1];
        }
    }
}

// ---------------- launcher --------------------------------------------------------
extern "C" void kernel_launch(void* const* d_in, const int* in_sizes, int n_in,
                              void* d_out, int out_size)
{
    const float* x  = (const float*)d_in[0];
    const void*  ei = d_in[1];
    const float* W1 = (const float*)d_in[2];
    const float* b1 = (const float*)d_in[3];
    const float* W2 = (const float*)d_in[4];
    const float* b2 = (const float*)d_in[5];
    const float* W3 = (const float*)d_in[6];
    const float* b3 = (const float*)d_in[7];
    const float* W4 = (const float*)d_in[8];
    const float* b4 = (const float*)d_in[9];
    const float* Wc = (const float*)d_in[10];
    const float* bc = (const float*)d_in[11];
    float* out = (float*)d_out;

    const int nb = (N_NODES + TB - 1) / TB;
    const int wb = (N_NODES * 32 + TB - 1) / TB;  // one warp per node

    k_init<<<nb, TB>>>(ei);            // 0
    k_count_fill<<<EB, TB>>>(ei);      // 1
    k_gemm1<<<G1B, TB>>>(x, W1);       // 2
    k_f1<<<wb, TB>>>(b1, W2);          // 3  (profiled)
    k_f2<<<wb, TB>>>(b2, W3);          // 4
    k_f3<<<wb, TB>>>(b3, W4);          // 5
    k_f4<<<wb, TB>>>(b4, Wc, bc, out); // 6
}